// round 6
// baseline (speedup 1.0000x reference)
#include <cuda_runtime.h>

#define NBLK 128
#define NTHR 384
#define B_ 2
#define M_ 768
#define N_ 512
#define MN_ (M_*N_)
#define AW (1.0f/768.0f)
#define BW (1.0f/512.0f)
#define EPSI 20.0f
#define RPB 12            // rows per block for init/copy (128*12 = 1536)
#define SRPB 24           // Sinkhorn rows per active block (32 blocks/batch)
#define AS_STRIDE 98
#define AS_BUF (16*AS_STRIDE)
#define BS_BUF (16*64)

// dynamic smem layout (floats)
#define OFF_KS   0          // 24*512 = 12288   (As/Bs aliased at 0..5184)
#define OFF_TS   12288      // 512
#define OFF_RED  12800      // 384
#define OFF_LOC  13184      // 24
#define SMEM_FLOATS 13208
#define SMEM_BYTES  (SMEM_FLOATS*4)

typedef unsigned long long ull;

// ---------------- device scratch ----------------
__device__ float g_P [B_*MN_];
__device__ float g_Km[B_*MN_];
__device__ float g_T [B_*MN_];
__device__ float g_rm[B_*M_];
__device__ float g_t1[B_*M_];
__device__ float g_t2[B_*N_];
__device__ float g_csum[3][B_*N_];
__device__ float g_cp[128];
__device__ float g_acc[4];
__device__ unsigned g_bar[128];  // [0] b0-full, [32] b1-full, [64] b0-sink, [96] b1-sink

__global__ void reset_kernel() {
    g_bar[0] = 0u; g_bar[32] = 0u; g_bar[64] = 0u; g_bar[96] = 0u;
}

// ---------------- barrier primitives ----------------
__device__ __forceinline__ void bar_arrive(unsigned* ctr) {
    asm volatile("red.release.gpu.global.add.u32 [%0], %1;"
                 :: "l"(ctr), "r"(1u) : "memory");
}
__device__ __forceinline__ void bar_wait(unsigned* ctr, unsigned target) {
    unsigned v0, v1, v2, v3;
    while (true) {
        asm volatile("ld.relaxed.gpu.global.b32 %0, [%4];\n\t"
                     "ld.relaxed.gpu.global.b32 %1, [%4];\n\t"
                     "ld.relaxed.gpu.global.b32 %2, [%4];\n\t"
                     "ld.relaxed.gpu.global.b32 %3, [%4];"
                     : "=r"(v0), "=r"(v1), "=r"(v2), "=r"(v3) : "l"(ctr));
        if (v3 >= target || v2 >= target || v1 >= target || v0 >= target) break;
    }
    asm volatile("fence.acq_rel.gpu;" ::: "memory");
}
// full-batch barrier (64 blocks)
__device__ __forceinline__ void gsync(unsigned &gen, unsigned* ctr) {
    ++gen;
    __syncthreads();
    if (threadIdx.x == 0) { bar_arrive(ctr); bar_wait(ctr, gen * 64u); }
    __syncthreads();
}
// sinkhorn barrier (32 active blocks)
__device__ __forceinline__ void ssync(unsigned &gen2, unsigned* ctr) {
    ++gen2;
    __syncthreads();
    if (threadIdx.x == 0) { bar_arrive(ctr); bar_wait(ctr, gen2 * 32u); }
    __syncthreads();
}

// ---------------- packed f32x2 helpers ----------------
__device__ __forceinline__ void fma2(ull &d, ull a, ull b) {
    asm("fma.rn.f32x2 %0, %1, %2, %0;" : "+l"(d) : "l"(a), "l"(b));
}
__device__ __forceinline__ ull splat(float x) {
    ull r; asm("mov.b64 %0, {%1, %1};" : "=l"(r) : "f"(x)); return r;
}

// ---------------- GEMM tile 96x64 (128 tiles), 384 thr, micro 4x4 ----------
template<int MODE>
__device__ void gemm_tile(int tile, const float* __restrict__ D1,
                          const float* __restrict__ D2,
                          float* As, float* Bs, float* red) {
    const int Kd  = (MODE == 0) ? N_ : M_;
    const int lda = (MODE == 0) ? N_ : M_;
    int b = tile >> 6;
    int r = tile & 63;
    int row0 = (r >> 3) * 96;
    int col0 = (r & 7) * 64;
    const float* A  = (MODE == 0) ? (g_P + (size_t)b*MN_) : (D1 + (size_t)b*M_*M_);
    const float* Bm = (MODE == 0) ? (D2 + (size_t)b*(size_t)N_*N_)
                    : (MODE == 1) ? (g_T + (size_t)b*MN_)
                                  : (g_P + (size_t)b*MN_);
    int tid = threadIdx.x;
    int tx = tid & 15, ty = tid >> 4;

    int lr = tid >> 2;
    int lk = (tid & 3) * 4;
    const float* ApL = A + (size_t)(row0 + lr)*lda + lk;
    int brow = tid >> 4, bq = tid & 15;
    const float* BpL = Bm + (size_t)brow*N_ + col0 + bq*4;

    ull acc[2][4];
    #pragma unroll
    for (int i = 0; i < 2; i++)
        #pragma unroll
        for (int j = 0; j < 4; j++) acc[i][j] = 0ull;

    float4 pa = *(const float4*)(ApL);
    float4 pb;
    if (tid < 256) pb = *(const float4*)(BpL);

    int buf = 0;
    for (int k0 = 0; k0 < Kd; k0 += 16) {
        float* Asb = As + buf*AS_BUF;
        float* Bsb = Bs + buf*BS_BUF;
        Asb[(lk+0)*AS_STRIDE + lr] = pa.x;
        Asb[(lk+1)*AS_STRIDE + lr] = pa.y;
        Asb[(lk+2)*AS_STRIDE + lr] = pa.z;
        Asb[(lk+3)*AS_STRIDE + lr] = pa.w;
        if (tid < 256) *(float4*)&Bsb[brow*64 + bq*4] = pb;
        if (k0 + 16 < Kd) {
            pa = *(const float4*)(ApL + k0 + 16);
            if (tid < 256) pb = *(const float4*)(BpL + (size_t)(k0+16)*N_);
        }
        __syncthreads();
        #pragma unroll
        for (int k = 0; k < 16; k++) {
            const float* ap = Asb + k*AS_STRIDE + ty*4;
            ull a01 = *(const ull*)(ap);
            ull a23 = *(const ull*)(ap + 2);
            float4 b4 = *(const float4*)&Bsb[k*64 + tx*4];
            ull b0 = splat(b4.x), b1 = splat(b4.y), b2 = splat(b4.z), b3 = splat(b4.w);
            fma2(acc[0][0], a01, b0); fma2(acc[0][1], a01, b1);
            fma2(acc[0][2], a01, b2); fma2(acc[0][3], a01, b3);
            fma2(acc[1][0], a23, b0); fma2(acc[1][1], a23, b1);
            fma2(acc[1][2], a23, b2); fma2(acc[1][3], a23, b3);
        }
        buf ^= 1;
    }

    float cS[4][4];
    #pragma unroll
    for (int p = 0; p < 2; p++)
        #pragma unroll
        for (int j = 0; j < 4; j++) {
            union { ull u; float f[2]; } cv; cv.u = acc[p][j];
            cS[2*p][j]   = cv.f[0];
            cS[2*p+1][j] = cv.f[1];
        }

    if (MODE == 0) {
        float* Cb = g_T + (size_t)b*MN_;
        #pragma unroll
        for (int rr = 0; rr < 4; rr++) {
            int row = row0 + ty*4 + rr;
            float4 v = make_float4(cS[rr][0], cS[rr][1], cS[rr][2], cS[rr][3]);
            *(float4*)(Cb + (size_t)row*N_ + col0 + tx*4) = v;
        }
    } else if (MODE == 1) {
        float* Cb = g_Km + (size_t)b*MN_;
        const float* t1b = g_t1 + b*M_;
        const float* t2b = g_t2 + b*N_;
        float t20 = t2b[col0+tx*4+0], t21 = t2b[col0+tx*4+1];
        float t22 = t2b[col0+tx*4+2], t23 = t2b[col0+tx*4+3];
        #pragma unroll
        for (int rr = 0; rr < 4; rr++) {
            int row = row0 + ty*4 + rr;
            float t1v = t1b[row];
            float4 v;
            v.x = __expf((2.0f*cS[rr][0] - t1v - t20) * EPSI);
            v.y = __expf((2.0f*cS[rr][1] - t1v - t21) * EPSI);
            v.z = __expf((2.0f*cS[rr][2] - t1v - t22) * EPSI);
            v.w = __expf((2.0f*cS[rr][3] - t1v - t23) * EPSI);
            *(float4*)(Cb + (size_t)row*N_ + col0 + tx*4) = v;
        }
    } else {
        const float* Tb = g_T + (size_t)b*MN_;
        float local = 0.f;
        #pragma unroll
        for (int rr = 0; rr < 4; rr++) {
            int row = row0 + ty*4 + rr;
            float4 tv = *(const float4*)(Tb + (size_t)row*N_ + col0 + tx*4);
            local += cS[rr][0]*tv.x + cS[rr][1]*tv.y + cS[rr][2]*tv.z + cS[rr][3]*tv.w;
        }
        red[tid] = local;
        __syncthreads();
        if (tid < 128) red[tid] += red[tid + 128] + red[tid + 256];
        __syncthreads();
        for (int st = 64; st; st >>= 1) {
            if (tid < st) red[tid] += red[tid + st];
            __syncthreads();
        }
        if (!tid) g_cp[tile] = red[0];
    }
}

// ---------------- t1 = (D1.^2) @ rm  (warp per row, 12 warps) --------------
__device__ void sqmv_t1(const float* __restrict__ D1, int bid, int wid, int lane) {
    int fi = bid*RPB + wid;
    int b2 = fi >= M_;
    int i  = fi - b2*M_;
    const float4* row = (const float4*)(D1 + ((size_t)b2*M_ + i)*M_);
    const float4* rmb = (const float4*)(g_rm + b2*M_);
    float s = 0.f;
    for (int q = lane; q < 192; q += 32) {
        float4 v  = row[q];
        float4 r4 = rmb[q];
        s += v.x*v.x*r4.x + v.y*v.y*r4.y + v.z*v.z*r4.z + v.w*v.w*r4.w;
    }
    #pragma unroll
    for (int o = 16; o; o >>= 1) s += __shfl_xor_sync(0xffffffffu, s, o);
    if (!lane) g_t1[fi] = s;
}

// ---------------- persistent mega-kernel ----------------
__global__ void __launch_bounds__(NTHR)
gw_kernel(const float* __restrict__ D1, const float* __restrict__ D2,
          float* __restrict__ out, int out_size) {
    extern __shared__ float dyn[];
    float* sKs  = dyn + OFF_KS;
    float* As   = dyn + 0;           // alias inside sKs (disjoint phases)
    float* Bs   = dyn + 2*AS_BUF;    // 3136..5184, still inside sKs
    float* tS   = dyn + OFF_TS;
    float* sRed = dyn + OFF_RED;
    float* sLoc = dyn + OFF_LOC;

    int bid = blockIdx.x, tid = threadIdx.x;
    int wid = tid >> 5, lane = tid & 31;
    unsigned gen = 0, gen2 = 0;
    int bb = bid >> 6;                       // batch
    int lid6 = bid & 63;
    bool active = lid6 < 32;                 // Sinkhorn-active blocks
    unsigned* fctr = &g_bar[bb*32];
    unsigned* sctr = &g_bar[64 + bb*32];
    size_t rowbase = (size_t)bid * (RPB*N_); // init/copy ownership (12 rows)
    int srow0 = bb*M_ + lid6*SRPB;           // Sinkhorn ownership (24 rows)
    size_t sbase = (size_t)srow0 * N_;

    // ---------- Phase I ----------
    for (int idx = tid; idx < RPB*N_; idx += NTHR) g_P[rowbase + idx] = AW*BW;
    if (tid < RPB) g_rm[bid*RPB + tid] = AW;
    if (wid < 8) {
        int gw2 = bid*8 + wid;
        int b2 = gw2 >> 9, j = gw2 & 511;
        const float4* row = (const float4*)(D2 + ((size_t)b2*N_ + j)*N_);
        float s = 0.f;
        for (int q = lane; q < 128; q += 32) {
            float4 v = row[q];
            s += v.x*v.x + v.y*v.y + v.z*v.z + v.w*v.w;
        }
        #pragma unroll
        for (int o = 16; o; o >>= 1) s += __shfl_xor_sync(0xffffffffu, s, o);
        if (!lane) g_t2[gw2] = BW * s;
    }
    if (lid6 == 0)
        for (int idx = tid; idx < N_; idx += NTHR) g_csum[0][bb*N_ + idx] = 0.f;
    gsync(gen, fctr);

    int git = 0;
    for (int outer = 0; outer < 10; outer++) {
        // Phase A: T = P@D2 + t1 sqmv
        gemm_tile<0>(bid, D1, D2, As, Bs, sRed);
        sqmv_t1(D1, bid, wid, lane);
        gsync(gen, fctr);

        // Phase B: Km = exp(...)
        gemm_tile<1>(bid, D1, D2, As, Bs, sRed);
        gsync(gen, fctr);

        // Sinkhorn: 20 iterations on 32 active blocks/batch
        if (active) {
            for (int it = 0; it < 20; it++, git++) {
                if (it == 0) {
                    const float4* src = (const float4*)(g_Km + sbase);
                    float4* dst = (float4*)sKs;
                    for (int idx = tid; idx < SRPB*N_/4; idx += NTHR) dst[idx] = src[idx];
                    __syncthreads();
                }
                // u-dots: warp w handles rows 2w and 2w+1 in one pass
                {
                    int r0 = 2*wid, r1 = 2*wid + 1;
                    float s0 = 0.f, s1 = 0.f;
                    if (it == 0) {
                        for (int q = lane; q < 128; q += 32) {
                            float4 v0 = *(const float4*)&sKs[r0*N_ + q*4];
                            float4 v1 = *(const float4*)&sKs[r1*N_ + q*4];
                            s0 += v0.x + v0.y + v0.z + v0.w;
                            s1 += v1.x + v1.y + v1.z + v1.w;
                        }
                    } else {
                        for (int q = lane; q < 128; q += 32) {
                            float4 t4 = *(const float4*)&tS[q*4];
                            float4 v0 = *(const float4*)&sKs[r0*N_ + q*4];
                            float4 v1 = *(const float4*)&sKs[r1*N_ + q*4];
                            s0 += v0.x*t4.x + v0.y*t4.y + v0.z*t4.z + v0.w*t4.w;
                            s1 += v1.x*t4.x + v1.y*t4.y + v1.z*t4.z + v1.w*t4.w;
                        }
                    }
                    #pragma unroll
                    for (int o = 16; o; o >>= 1) {
                        s0 += __shfl_xor_sync(0xffffffffu, s0, o);
                        s1 += __shfl_xor_sync(0xffffffffu, s1, o);
                    }
                    if (!lane) {
                        sLoc[r0] = __fdividef(AW, s0);
                        sLoc[r1] = __fdividef(AW, s1);
                    }
                }
                __syncthreads();
                // column partials -> atomic accumulate; zero next buffer
                {
                    int p = git % 3;
                    float a0 = 0.f;
                    #pragma unroll
                    for (int rr = 0; rr < SRPB; rr++)
                        a0 += sKs[rr*N_ + tid] * sLoc[rr];
                    atomicAdd(&g_csum[p][bb*N_ + tid], a0);
                    if (tid < 128) {
                        float a1 = 0.f;
                        #pragma unroll
                        for (int rr = 0; rr < SRPB; rr++)
                            a1 += sKs[rr*N_ + tid + 384] * sLoc[rr];
                        atomicAdd(&g_csum[p][bb*N_ + tid + 384], a1);
                    }
                    int pn = (p + 1 == 3) ? 0 : p + 1;
                    if (tid < 16) g_csum[pn][bb*N_ + lid6*16 + tid] = 0.f;
                }
                ssync(gen2, sctr);
                // t recompute
                {
                    int p = git % 3;
                    tS[tid] = __fdividef(BW, g_csum[p][bb*N_ + tid]);
                    if (tid < 128)
                        tS[tid + 384] = __fdividef(BW, g_csum[p][bb*N_ + tid + 384]);
                }
                __syncthreads();
            }

            // P update + row masses (dual rows per warp)
            {
                int r0 = 2*wid, r1 = 2*wid + 1;
                float s0 = 0.f, s1 = 0.f;
                for (int q = lane; q < 128; q += 32) {
                    float4 t4 = *(const float4*)&tS[q*4];
                    float4 v0 = *(const float4*)&sKs[r0*N_ + q*4];
                    float4 v1 = *(const float4*)&sKs[r1*N_ + q*4];
                    s0 += v0.x*t4.x + v0.y*t4.y + v0.z*t4.z + v0.w*t4.w;
                    s1 += v1.x*t4.x + v1.y*t4.y + v1.z*t4.z + v1.w*t4.w;
                }
                #pragma unroll
                for (int o = 16; o; o >>= 1) {
                    s0 += __shfl_xor_sync(0xffffffffu, s0, o);
                    s1 += __shfl_xor_sync(0xffffffffu, s1, o);
                }
                if (!lane) {
                    g_rm[srow0 + r0] = sLoc[r0] * s0;
                    g_rm[srow0 + r1] = sLoc[r1] * s1;
                }
            }
            for (int c = tid; c < SRPB*N_; c += NTHR) {
                int rr = c >> 9, j = c & 511;
                g_P[sbase + c] = sLoc[rr] * sKs[c] * tS[j];
            }
        } else {
            git += 20;
        }
        gsync(gen, fctr);
    }

    // ---------- Final cost ----------
    gemm_tile<0>(bid, D1, D2, As, Bs, sRed);
    sqmv_t1(D1, bid, wid, lane);
    gsync(gen, fctr);

    gemm_tile<2>(bid, D1, D2, As, Bs, sRed);
    __syncthreads();
    if (lid6 == 0) {                       // blocks 0, 64: rm . t1
        float s = 0.f;
        for (int i = tid; i < M_; i += NTHR) s += g_rm[bb*M_ + i] * g_t1[bb*M_ + i];
        sRed[tid] = s;
        __syncthreads();
        if (tid < 128) sRed[tid] += sRed[tid + 128] + sRed[tid + 256];
        __syncthreads();
        for (int st = 64; st; st >>= 1) {
            if (tid < st) sRed[tid] += sRed[tid + st];
            __syncthreads();
        }
        if (!tid) g_acc[bb] = sRed[0];
    } else if (lid6 == 1) {                // blocks 1, 65: BW * sum t2
        float s = 0.f;
        for (int j = tid; j < N_; j += NTHR) s += g_t2[bb*N_ + j];
        sRed[tid] = s;
        __syncthreads();
        if (tid < 128) sRed[tid] += sRed[tid + 128] + sRed[tid + 256];
        __syncthreads();
        for (int st = 64; st; st >>= 1) {
            if (tid < st) sRed[tid] += sRed[tid + st];
            __syncthreads();
        }
        if (!tid) g_acc[2 + bb] = BW * sRed[0];
    }
    gsync(gen, fctr);

    // outputs
    if (lid6 == 0 && tid == 0) {
        float cr = 0.f;
        for (int t = 0; t < 64; t++) cr += g_cp[bb*64 + t];
        out[bb] = g_acc[bb] + g_acc[2 + bb] - 2.0f*cr;
    }
    if (out_size > 2) {
        const float2* src = (const float2*)(g_P + rowbase);
        float2* dst = (float2*)(out + 2 + rowbase);
        for (int idx = tid; idx < RPB*N_/2; idx += NTHR) dst[idx] = src[idx];
    }
}

// ---------------- host driver ----------------
extern "C" void kernel_launch(void* const* d_in, const int* in_sizes, int n_in,
                              void* d_out, int out_size) {
    const float* D1 = (const float*)d_in[0];
    const float* D2 = (const float*)d_in[1];
    if (n_in >= 2 && in_sizes[0] == B_*N_*N_ && in_sizes[1] == B_*M_*M_) {
        const float* tmp = D1; D1 = D2; D2 = tmp;
    }
    float* out = (float*)d_out;

    cudaFuncSetAttribute(gw_kernel, cudaFuncAttributeMaxDynamicSharedMemorySize,
                         SMEM_BYTES);
    reset_kernel<<<1, 1>>>();
    gw_kernel<<<NBLK, NTHR, SMEM_BYTES>>>(D1, D2, out, out_size);
}